// round 10
// baseline (speedup 1.0000x reference)
#include <cuda_runtime.h>
#include <cstdint>

#define B_SZ   256
#define F_SZ   128
#define DEPTHD 6
#define C_SZ   100
#define L_SZ   64
#define NTREE  8192
#define KTOT   ((size_t)NTREE * L_SZ)     /* 524288 */
#define NSLICE 148                        /* one CTA per tree-slice */
#define N_PAD  104                        /* C padded: 13 n-tiles of 8 */
#define SST    68                         /* sel smem stride (words) */
#define HST    36                         /* accum smem stride (words), 36 mod 32 = 4 */
#define NTHR   640                        /* 16 consumer + 4 producer warps */
#define NCONS  512                        /* consumer threads */
#define STAGE_WORDS (256 * HST + N_PAD * HST)   /* 12960 words/stage */
#define W_SCALE   512.0f
#define W_INV     0.001953125f            /* 1/512 */

/* scratch: fv[m = tree*6+d][b], 49152 x 256 floats = 50.3 MB */
__device__ float g_fv[NTREE * DEPTHD * B_SZ];

/* ---- helpers ---- */
__device__ __forceinline__ uint32_t f2h2(float lo, float hi) {
    uint32_t u; asm("cvt.rn.f16x2.f32 %0, %1, %2;" : "=r"(u) : "f"(hi), "f"(lo)); return u;
}
__device__ __forceinline__ void mma16(float c[4],
                                      uint32_t a0, uint32_t a1, uint32_t a2, uint32_t a3,
                                      uint32_t b0, uint32_t b1) {
    asm volatile(
        "mma.sync.aligned.m16n8k16.row.col.f32.f16.f16.f32 "
        "{%0,%1,%2,%3}, {%4,%5,%6,%7}, {%8,%9}, {%0,%1,%2,%3};"
        : "+f"(c[0]), "+f"(c[1]), "+f"(c[2]), "+f"(c[3])
        : "r"(a0), "r"(a1), "r"(a2), "r"(a3), "r"(b0), "r"(b1));
}
#define BAR_SYNC(id)   asm volatile("bar.sync %0, %1;"   :: "r"(id), "r"(NTHR) : "memory")
#define BAR_ARRIVE(id) asm volatile("bar.arrive %0, %1;" :: "r"(id), "r"(NTHR) : "memory")

/* ================= kernel 1: selector GEMM + sigmoid (fp16 m16n8k16) ========= */
__global__ void __launch_bounds__(256) sel_fp16(const float* __restrict__ x,
                                                const float* __restrict__ selW,
                                                const float* __restrict__ selb) {
    extern __shared__ uint32_t sm[];
    uint32_t* As = sm;                 /* 128 x SST */
    uint32_t* Bs = sm + 128 * SST;     /* 64 x SST  */

    const int tid = threadIdx.x;
    const int wid = tid >> 5, lane = tid & 31;
    const int g = lane >> 2, tg = lane & 3;
    const int mw = wid & 3, nw = wid >> 2;
    const int row0 = blockIdx.x * 128, col0 = blockIdx.y * 64;

#pragma unroll
    for (int it = 0; it < 16; it++) {
        int e = tid + it * 256;
        int r = e >> 5, q = e & 31;
        float4 v = *(const float4*)(selW + (size_t)(row0 + r) * F_SZ + q * 4);
        uint2 w; w.x = f2h2(v.x, v.y); w.y = f2h2(v.z, v.w);
        *(uint2*)&As[r * SST + q * 2] = w;
    }
#pragma unroll
    for (int it = 0; it < 8; it++) {
        int e = tid + it * 256;
        int r = e >> 5, q = e & 31;
        float4 v = *(const float4*)(x + (size_t)(col0 + r) * F_SZ + q * 4);
        uint2 w; w.x = f2h2(v.x, v.y); w.y = f2h2(v.z, v.w);
        *(uint2*)&Bs[r * SST + q * 2] = w;
    }
    __syncthreads();

    float acc[2][4][4];
#pragma unroll
    for (int mi = 0; mi < 2; mi++)
#pragma unroll
        for (int ni = 0; ni < 4; ni++)
#pragma unroll
            for (int q = 0; q < 4; q++) acc[mi][ni][q] = 0.f;

#pragma unroll
    for (int c = 0; c < 8; c++) {
        uint32_t a[2][4], b[4][2];
#pragma unroll
        for (int mi = 0; mi < 2; mi++) {
            int mb = mw * 32 + mi * 16;
            a[mi][0] = As[(mb + g) * SST + 8 * c + tg];
            a[mi][1] = As[(mb + g + 8) * SST + 8 * c + tg];
            a[mi][2] = As[(mb + g) * SST + 8 * c + tg + 4];
            a[mi][3] = As[(mb + g + 8) * SST + 8 * c + tg + 4];
        }
#pragma unroll
        for (int ni = 0; ni < 4; ni++) {
            int nb = nw * 32 + ni * 8 + g;
            b[ni][0] = Bs[nb * SST + 8 * c + tg];
            b[ni][1] = Bs[nb * SST + 8 * c + tg + 4];
        }
#pragma unroll
        for (int mi = 0; mi < 2; mi++)
#pragma unroll
            for (int ni = 0; ni < 4; ni++)
                mma16(acc[mi][ni], a[mi][0], a[mi][1], a[mi][2], a[mi][3],
                      b[ni][0], b[ni][1]);
    }

#pragma unroll
    for (int mi = 0; mi < 2; mi++) {
        int m = row0 + mw * 32 + mi * 16 + g;
        float b0 = selb[m], b1 = selb[m + 8];
#pragma unroll
        for (int ni = 0; ni < 4; ni++) {
            int bcol = col0 + nw * 32 + ni * 8 + tg * 2;
            float2 v0, v1;
            v0.x = 1.f / (1.f + __expf(-(acc[mi][ni][0] + b0)));
            v0.y = 1.f / (1.f + __expf(-(acc[mi][ni][1] + b0)));
            v1.x = 1.f / (1.f + __expf(-(acc[mi][ni][2] + b1)));
            v1.y = 1.f / (1.f + __expf(-(acc[mi][ni][3] + b1)));
            *(float2*)&g_fv[(size_t)m * B_SZ + bcol] = v0;
            *(float2*)&g_fv[(size_t)(m + 8) * B_SZ + bcol] = v1;
        }
    }
}

/* ================= kernel 2: warp-specialized fused leaf + fp16 GEMM =========
 * grid = 148 CTAs, 640 threads: warps 0-15 consumers, 16-19 producers.
 * 3-stage smem ring; named-barrier handshake (full 1-3, empty 4-6).
 * Consumers: 8 mw x 2 nw, 2 m-tiles x {7,6} n-tiles x 4 k-chunks, mma only.
 * Producers: leaf gen (2 b-rows/thread, 64 leaves each) + W staging (13 f4). */

/* producer: stage tree t into ring stage s */
__device__ __forceinline__ void prod_stage(uint32_t* Ab, uint32_t* Bb, int t,
                                           const float* __restrict__ outW, int tid2) {
    /* ---- leaf tiles: rows tid2 and tid2+128 ---- */
#pragma unroll
    for (int k = 0; k < 2; k++) {
        const int row = tid2 + k * 128;
        const float* fp = g_fv + (size_t)t * (DEPTHD * B_SZ) + row;
        float p0 = fp[0], p1 = fp[256], p2 = fp[512];
        float p3 = fp[768], p4 = fp[1024], p5 = fp[1280];
        float a1[2], a2[4], a3[8], a4[16];
        a1[0] = p1; a1[1] = 1.f - p1;
#pragma unroll
        for (int i = 0; i < 2; i++) { a2[2*i] = a1[i] * p2; a2[2*i+1] = a1[i] * (1.f - p2); }
#pragma unroll
        for (int i = 0; i < 4; i++) { a3[2*i] = a2[i] * p3; a3[2*i+1] = a2[i] * (1.f - p3); }
#pragma unroll
        for (int i = 0; i < 8; i++) { a4[2*i] = a3[i] * p4; a4[2*i+1] = a3[i] * (1.f - p4); }
        float q0 = 1.f - p0, q5 = 1.f - p5;
        uint32_t* dst = Ab + row * HST;
#pragma unroll
        for (int h = 0; h < 2; h++) {          /* l bit5 = d0 bit */
            float s = h ? q0 : p0;
#pragma unroll
            for (int i = 0; i < 4; i++) {
                float e0 = s * a4[4*i],     e1 = s * a4[4*i + 1];
                float e2 = s * a4[4*i + 2], e3 = s * a4[4*i + 3];
                uint4 w;
                w.x = f2h2(e0 * p5, e0 * q5);
                w.y = f2h2(e1 * p5, e1 * q5);
                w.z = f2h2(e2 * p5, e2 * q5);
                w.w = f2h2(e3 * p5, e3 * q5);
                *(uint4*)(dst + h * 16 + i * 4) = w;
            }
        }
    }
    /* ---- W tile: 104 x 16 = 1664 float4 over 128 threads ---- */
    {
        const float* wp = outW + (size_t)t * L_SZ;
#pragma unroll
        for (int it = 0; it < 13; it++) {
            int e = tid2 + it * 128;
            int c = e >> 4, q = e & 15;
            uint2 w;
            if (c < C_SZ) {
                float4 v = *(const float4*)(wp + (size_t)c * KTOT + q * 4);
                w.x = f2h2(v.x * W_SCALE, v.y * W_SCALE);
                w.y = f2h2(v.z * W_SCALE, v.w * W_SCALE);
            } else {
                w.x = 0u; w.y = 0u;
            }
            *(uint2*)&Bb[c * HST + q * 2] = w;
        }
    }
}

template <int NT>
__device__ __forceinline__ void mma_trees(float acc[2][7][4],
                                          const uint32_t* __restrict__ As,
                                          const uint32_t* __restrict__ Bs,
                                          int mw, int nw, int g, int tg) {
#pragma unroll
    for (int c = 0; c < 4; c++) {
        uint32_t a[2][4], b[NT][2];
#pragma unroll
        for (int mi = 0; mi < 2; mi++) {
            int mb = mw * 32 + mi * 16;
            a[mi][0] = As[(mb + g) * HST + 8 * c + tg];
            a[mi][1] = As[(mb + g + 8) * HST + 8 * c + tg];
            a[mi][2] = As[(mb + g) * HST + 8 * c + tg + 4];
            a[mi][3] = As[(mb + g + 8) * HST + 8 * c + tg + 4];
        }
#pragma unroll
        for (int ni = 0; ni < NT; ni++) {
            int nb = nw * 56 + ni * 8 + g;
            b[ni][0] = Bs[nb * HST + 8 * c + tg];
            b[ni][1] = Bs[nb * HST + 8 * c + tg + 4];
        }
#pragma unroll
        for (int mi = 0; mi < 2; mi++)
#pragma unroll
            for (int ni = 0; ni < NT; ni++)
                mma16(acc[mi][ni], a[mi][0], a[mi][1], a[mi][2], a[mi][3],
                      b[ni][0], b[ni][1]);
    }
}

__global__ void __launch_bounds__(NTHR, 1) accum_ws(const float* __restrict__ outW,
                                                    const float* __restrict__ outb,
                                                    float* __restrict__ out) {
    extern __shared__ uint32_t sm[];   /* 3 stages x STAGE_WORDS */

    const int tid = threadIdx.x;
    const int slice = blockIdx.x;
    const int t0 = (slice * NTREE) / NSLICE;
    const int t1 = ((slice + 1) * NTREE) / NSLICE;

    if (tid >= NCONS) {
        /* ================= producer warps ================= */
        const int tid2 = tid - NCONS;   /* 0..127 */
        for (int t = t0; t < t1; t++) {
            const int it = t - t0;
            const int s = it - (it / 3) * 3;
            if (it >= 3) BAR_SYNC(4 + s);                /* wait stage empty */
            uint32_t* Ab = sm + s * STAGE_WORDS;
            uint32_t* Bb = Ab + 256 * HST;
            prod_stage(Ab, Bb, t, outW, tid2);
            BAR_ARRIVE(1 + s);                           /* mark stage full */
        }
        return;
    }

    /* ================= consumer warps ================= */
    const int wid = tid >> 5, lane = tid & 31;
    const int g = lane >> 2, tg = lane & 3;
    const int mw = wid & 7, nw = wid >> 3;

    float acc[2][7][4];
#pragma unroll
    for (int mi = 0; mi < 2; mi++)
#pragma unroll
        for (int ni = 0; ni < 7; ni++)
#pragma unroll
            for (int q = 0; q < 4; q++) acc[mi][ni][q] = 0.f;

    for (int t = t0; t < t1; t++) {
        const int it = t - t0;
        const int s = it - (it / 3) * 3;
        BAR_SYNC(1 + s);                                 /* wait stage full */
        const uint32_t* As = sm + s * STAGE_WORDS;
        const uint32_t* Bs = As + 256 * HST;
        if (nw == 0) mma_trees<7>(acc, As, Bs, mw, nw, g, tg);
        else         mma_trees<6>(acc, As, Bs, mw, nw, g, tg);
        BAR_ARRIVE(4 + s);                               /* mark stage empty */
    }

    /* epilogue: atomicAdd (undo x512 W scale); CTA 0 also adds the bias */
    const int ntiles = nw ? 6 : 7;
    const bool addb = (blockIdx.x == 0);
#pragma unroll
    for (int mi = 0; mi < 2; mi++) {
        int row = mw * 32 + mi * 16 + g;
        float* op0 = out + (size_t)row * C_SZ;
        float* op1 = out + (size_t)(row + 8) * C_SZ;
#pragma unroll
        for (int ni = 0; ni < 7; ni++) {
            if (ni >= ntiles) break;
            int col = nw * 56 + ni * 8 + tg * 2;
            if (col < C_SZ) {
                float bb = addb ? outb[col] : 0.f;
                atomicAdd(op0 + col, acc[mi][ni][0] * W_INV + bb);
                atomicAdd(op1 + col, acc[mi][ni][2] * W_INV + bb);
            }
            if (col + 1 < C_SZ) {
                float bb = addb ? outb[col + 1] : 0.f;
                atomicAdd(op0 + col + 1, acc[mi][ni][1] * W_INV + bb);
                atomicAdd(op1 + col + 1, acc[mi][ni][3] * W_INV + bb);
            }
        }
    }
}

extern "C" void kernel_launch(void* const* d_in, const int* in_sizes, int n_in,
                              void* d_out, int out_size) {
    const float* x    = (const float*)d_in[0];
    const float* selW = (const float*)d_in[1];
    const float* selb = (const float*)d_in[2];
    const float* outW = (const float*)d_in[3];
    const float* outb = (const float*)d_in[4];
    float* out = (float*)d_out;

    cudaMemsetAsync(out, 0, (size_t)out_size * sizeof(float));

    size_t sel_smem = (size_t)(128 + 64) * SST * 4;                  /* 52224 B */
    cudaFuncSetAttribute(sel_fp16, cudaFuncAttributeMaxDynamicSharedMemorySize, (int)sel_smem);
    dim3 g1(384, 4);
    sel_fp16<<<g1, 256, sel_smem>>>(x, selW, selb);

    size_t acc_smem = (size_t)3 * STAGE_WORDS * 4;                   /* 155520 B */
    cudaFuncSetAttribute(accum_ws, cudaFuncAttributeMaxDynamicSharedMemorySize, (int)acc_smem);
    accum_ws<<<NSLICE, NTHR, acc_smem>>>(outW, outb, out);
}

// round 11
// speedup vs baseline: 1.1006x; 1.1006x over previous
#include <cuda_runtime.h>
#include <cstdint>

#define B_SZ   256
#define F_SZ   128
#define DEPTHD 6
#define C_SZ   100
#define L_SZ   64
#define NTREE  8192
#define KTOT   ((size_t)NTREE * L_SZ)     /* 524288 */
#define NSLICE 148                        /* one CTA per tree-slice */
#define N_PAD  104                        /* C padded: 13 n-tiles of 8 */
#define SST    68                         /* sel smem stride (words) */
#define HST    36                         /* accum smem stride (words), 36 mod 32 = 4 */
#define W_SCALE   512.0f
#define W_INV     0.001953125f            /* 1/512 */

/* scratch: fv[m = tree*6+d][b], 49152 x 256 floats = 50.3 MB */
__device__ float g_fv[NTREE * DEPTHD * B_SZ];

/* ---- helpers ---- */
__device__ __forceinline__ uint32_t f2h2(float lo, float hi) {
    uint32_t u; asm("cvt.rn.f16x2.f32 %0, %1, %2;" : "=r"(u) : "f"(hi), "f"(lo)); return u;
}
__device__ __forceinline__ uint32_t smem_u32(const void* p) {
    uint32_t a;
    asm("{ .reg .u64 t; cvta.to.shared.u64 t, %1; cvt.u32.u64 %0, t; }" : "=r"(a) : "l"(p));
    return a;
}
__device__ __forceinline__ void mma16(float c[4],
                                      uint32_t a0, uint32_t a1, uint32_t a2, uint32_t a3,
                                      uint32_t b0, uint32_t b1) {
    asm volatile(
        "mma.sync.aligned.m16n8k16.row.col.f32.f16.f16.f32 "
        "{%0,%1,%2,%3}, {%4,%5,%6,%7}, {%8,%9}, {%0,%1,%2,%3};"
        : "+f"(c[0]), "+f"(c[1]), "+f"(c[2]), "+f"(c[3])
        : "r"(a0), "r"(a1), "r"(a2), "r"(a3), "r"(b0), "r"(b1));
}
#define LDM_X4(r0, r1, r2, r3, addr) \
    asm volatile("ldmatrix.sync.aligned.m8n8.x4.shared.b16 {%0,%1,%2,%3}, [%4];" \
        : "=r"(r0), "=r"(r1), "=r"(r2), "=r"(r3) : "r"(addr))
#define LDM_X2(r0, r1, addr) \
    asm volatile("ldmatrix.sync.aligned.m8n8.x2.shared.b16 {%0,%1}, [%2];" \
        : "=r"(r0), "=r"(r1) : "r"(addr))

/* ================= kernel 1: selector GEMM + sigmoid (fp16 m16n8k16) ========= */
__global__ void __launch_bounds__(256) sel_fp16(const float* __restrict__ x,
                                                const float* __restrict__ selW,
                                                const float* __restrict__ selb) {
    extern __shared__ uint32_t sm[];
    uint32_t* As = sm;                 /* 128 x SST */
    uint32_t* Bs = sm + 128 * SST;     /* 64 x SST  */

    const int tid = threadIdx.x;
    const int wid = tid >> 5, lane = tid & 31;
    const int g = lane >> 2, tg = lane & 3;
    const int mw = wid & 3, nw = wid >> 2;
    const int row0 = blockIdx.x * 128, col0 = blockIdx.y * 64;

#pragma unroll
    for (int it = 0; it < 16; it++) {
        int e = tid + it * 256;
        int r = e >> 5, q = e & 31;
        float4 v = *(const float4*)(selW + (size_t)(row0 + r) * F_SZ + q * 4);
        uint2 w; w.x = f2h2(v.x, v.y); w.y = f2h2(v.z, v.w);
        *(uint2*)&As[r * SST + q * 2] = w;
    }
#pragma unroll
    for (int it = 0; it < 8; it++) {
        int e = tid + it * 256;
        int r = e >> 5, q = e & 31;
        float4 v = *(const float4*)(x + (size_t)(col0 + r) * F_SZ + q * 4);
        uint2 w; w.x = f2h2(v.x, v.y); w.y = f2h2(v.z, v.w);
        *(uint2*)&Bs[r * SST + q * 2] = w;
    }
    __syncthreads();

    float acc[2][4][4];
#pragma unroll
    for (int mi = 0; mi < 2; mi++)
#pragma unroll
        for (int ni = 0; ni < 4; ni++)
#pragma unroll
            for (int q = 0; q < 4; q++) acc[mi][ni][q] = 0.f;

#pragma unroll
    for (int c = 0; c < 8; c++) {
        uint32_t a[2][4], b[4][2];
#pragma unroll
        for (int mi = 0; mi < 2; mi++) {
            int mb = mw * 32 + mi * 16;
            a[mi][0] = As[(mb + g) * SST + 8 * c + tg];
            a[mi][1] = As[(mb + g + 8) * SST + 8 * c + tg];
            a[mi][2] = As[(mb + g) * SST + 8 * c + tg + 4];
            a[mi][3] = As[(mb + g + 8) * SST + 8 * c + tg + 4];
        }
#pragma unroll
        for (int ni = 0; ni < 4; ni++) {
            int nb = nw * 32 + ni * 8 + g;
            b[ni][0] = Bs[nb * SST + 8 * c + tg];
            b[ni][1] = Bs[nb * SST + 8 * c + tg + 4];
        }
#pragma unroll
        for (int mi = 0; mi < 2; mi++)
#pragma unroll
            for (int ni = 0; ni < 4; ni++)
                mma16(acc[mi][ni], a[mi][0], a[mi][1], a[mi][2], a[mi][3],
                      b[ni][0], b[ni][1]);
    }

#pragma unroll
    for (int mi = 0; mi < 2; mi++) {
        int m = row0 + mw * 32 + mi * 16 + g;
        float b0 = selb[m], b1 = selb[m + 8];
#pragma unroll
        for (int ni = 0; ni < 4; ni++) {
            int bcol = col0 + nw * 32 + ni * 8 + tg * 2;
            float2 v0, v1;
            v0.x = 1.f / (1.f + __expf(-(acc[mi][ni][0] + b0)));
            v0.y = 1.f / (1.f + __expf(-(acc[mi][ni][1] + b0)));
            v1.x = 1.f / (1.f + __expf(-(acc[mi][ni][2] + b1)));
            v1.y = 1.f / (1.f + __expf(-(acc[mi][ni][3] + b1)));
            *(float2*)&g_fv[(size_t)m * B_SZ + bcol] = v0;
            *(float2*)&g_fv[(size_t)(m + 8) * B_SZ + bcol] = v1;
        }
    }
}

/* ================= kernel 2: fused leaf + fp16 GEMM, prefetch + ldmatrix =====
 * grid = 148 CTAs, 512 threads, 1 CTA/SM. R9 reg-prefetch pipeline; fragment
 * loads via ldmatrix (A: 2x x4, B: 3x x4 + 1x x2 per k-chunk-set per tree). */
struct Pref {
    float p0, p1, p2, p3, p4, p5;     /* fv for this thread's (b row, lh) */
    float4 w[4];                      /* W slice elements (predicated)     */
};

__device__ __forceinline__ void load_pref(Pref& pr, int t,
                                          const float* __restrict__ outW,
                                          int tid, int b_local) {
    const float* fp = g_fv + (size_t)t * (DEPTHD * B_SZ) + b_local;
    pr.p0 = fp[0];    pr.p1 = fp[256];  pr.p2 = fp[512];
    pr.p3 = fp[768];  pr.p4 = fp[1024]; pr.p5 = fp[1280];
    const float* wp = outW + (size_t)t * L_SZ;
#pragma unroll
    for (int it = 0; it < 4; it++) {
        int e = tid + it * 512;
        int c = e >> 4, q = e & 15;
        if (e < N_PAD * 16 && c < C_SZ)
            pr.w[it] = *(const float4*)(wp + (size_t)c * KTOT + q * 4);
        else
            pr.w[it] = make_float4(0.f, 0.f, 0.f, 0.f);
    }
}

__device__ __forceinline__ void store_stage(const Pref& pr, uint32_t* Ab, uint32_t* Bb,
                                            int tid, int b_local, int lh) {
    /* ---- leaf tile: 2 threads per b row; lh = bit5 of l (d0 bit) ---- */
    {
        float g0 = lh ? (1.f - pr.p0) : pr.p0;
        float a1[2], a2[4], a3[8], a4[16];
        a1[0] = g0 * pr.p1; a1[1] = g0 * (1.f - pr.p1);
#pragma unroll
        for (int i = 0; i < 2; i++) { a2[2*i] = a1[i] * pr.p2; a2[2*i+1] = a1[i] * (1.f - pr.p2); }
#pragma unroll
        for (int i = 0; i < 4; i++) { a3[2*i] = a2[i] * pr.p3; a3[2*i+1] = a2[i] * (1.f - pr.p3); }
#pragma unroll
        for (int i = 0; i < 8; i++) { a4[2*i] = a3[i] * pr.p4; a4[2*i+1] = a3[i] * (1.f - pr.p4); }
        float p5 = pr.p5, q5 = 1.f - pr.p5;
        uint32_t* dst = Ab + b_local * HST + lh * 16;
#pragma unroll
        for (int i = 0; i < 4; i++) {
            uint4 w;
            w.x = f2h2(a4[4*i]     * p5, a4[4*i]     * q5);
            w.y = f2h2(a4[4*i + 1] * p5, a4[4*i + 1] * q5);
            w.z = f2h2(a4[4*i + 2] * p5, a4[4*i + 2] * q5);
            w.w = f2h2(a4[4*i + 3] * p5, a4[4*i + 3] * q5);
            *(uint4*)(dst + i * 4) = w;
        }
    }
    /* ---- W tile ---- */
#pragma unroll
    for (int it = 0; it < 4; it++) {
        int e = tid + it * 512;
        if (e < N_PAD * 16) {
            int c = e >> 4, q = e & 15;
            uint2 w;
            w.x = f2h2(pr.w[it].x * W_SCALE, pr.w[it].y * W_SCALE);
            w.y = f2h2(pr.w[it].z * W_SCALE, pr.w[it].w * W_SCALE);
            *(uint2*)&Bb[c * HST + q * 2] = w;
        }
    }
}

/* fragment loads via ldmatrix; lane->addr mapping reproduces the scalar layout:
 * A x4: mats {m0-7,k0},{m8-15,k0},{m0-7,k8},{m8-15,k8}; lane L: row mb+(L&15),
 *       colword (L>>4)*4.
 * B x4 (2 n-tiles): mats {n0-7,k0},{n0-7,k8},{n8-15,k0},{n8-15,k8}; lane L:
 *       row nb0+(L>>4)*8+(L&7), colword ((L>>3)&1)*4. x2 for the odd tile. */
template <int NT>
__device__ __forceinline__ void mma_trees(float acc[2][7][4],
                                          const uint32_t* __restrict__ As,
                                          const uint32_t* __restrict__ Bs,
                                          int mw, int nw, int lane) {
    const uint32_t a0ad = smem_u32(As + ((mw * 32 + (lane & 15)) * HST + (lane >> 4) * 4));
    const uint32_t b0ad = smem_u32(Bs + ((nw * 56 + (lane >> 4) * 8 + (lane & 7)) * HST
                                         + ((lane >> 3) & 1) * 4));
    const uint32_t b2ad = smem_u32(Bs + ((nw * 56 + 48 + (lane & 7)) * HST
                                         + ((lane >> 3) & 1) * 4));
#pragma unroll
    for (int c = 0; c < 4; c++) {
        uint32_t a[2][4], b[7][2];
        LDM_X4(a[0][0], a[0][1], a[0][2], a[0][3], a0ad + c * 32);
        LDM_X4(a[1][0], a[1][1], a[1][2], a[1][3], a0ad + 16 * HST * 4 + c * 32);
#pragma unroll
        for (int p = 0; p < NT / 2; p++)
            LDM_X4(b[2*p][0], b[2*p][1], b[2*p+1][0], b[2*p+1][1],
                   b0ad + p * 16 * HST * 4 + c * 32);
        if (NT & 1)
            LDM_X2(b[NT-1][0], b[NT-1][1], b2ad + c * 32);
#pragma unroll
        for (int mi = 0; mi < 2; mi++)
#pragma unroll
            for (int ni = 0; ni < NT; ni++)
                mma16(acc[mi][ni], a[mi][0], a[mi][1], a[mi][2], a[mi][3],
                      b[ni][0], b[ni][1]);
    }
}

__global__ void __launch_bounds__(512, 1) accum_512(const float* __restrict__ outW,
                                                    const float* __restrict__ outb,
                                                    float* __restrict__ out) {
    extern __shared__ uint32_t sm[];
    uint32_t* A0 = sm;                        /* 256*HST words */
    uint32_t* A1 = A0 + 256 * HST;
    uint32_t* B0 = A1 + 256 * HST;            /* 104*HST words */
    uint32_t* B1 = B0 + N_PAD * HST;

    const int tid = threadIdx.x;
    const int wid = tid >> 5, lane = tid & 31;
    const int g = lane >> 2, tg = lane & 3;
    const int mw = wid & 7, nw = wid >> 3;
    const int slice = blockIdx.x;
    const int t0 = (slice * NTREE) / NSLICE;
    const int t1 = ((slice + 1) * NTREE) / NSLICE;

    const int b_local = tid >> 1;
    const int lh = tid & 1;

    float acc[2][7][4];
#pragma unroll
    for (int mi = 0; mi < 2; mi++)
#pragma unroll
        for (int ni = 0; ni < 7; ni++)
#pragma unroll
            for (int q = 0; q < 4; q++) acc[mi][ni][q] = 0.f;

    Pref cur, nxt;
    load_pref(cur, t0, outW, tid, b_local);

    int t = t0;
    while (t < t1) {
        /* --- even step: consume cur, prefetch into nxt --- */
        {
            const int buf = (t - t0) & 1;
            store_stage(cur, buf ? A1 : A0, buf ? B1 : B0, tid, b_local, lh);
            if (t + 1 < t1) load_pref(nxt, t + 1, outW, tid, b_local);
            __syncthreads();
            const uint32_t* As = buf ? A1 : A0;
            const uint32_t* Bs = buf ? B1 : B0;
            if (nw == 0) mma_trees<7>(acc, As, Bs, mw, nw, lane);
            else         mma_trees<6>(acc, As, Bs, mw, nw, lane);
        }
        if (++t >= t1) break;
        /* --- odd step: consume nxt, prefetch into cur --- */
        {
            const int buf = (t - t0) & 1;
            store_stage(nxt, buf ? A1 : A0, buf ? B1 : B0, tid, b_local, lh);
            if (t + 1 < t1) load_pref(cur, t + 1, outW, tid, b_local);
            __syncthreads();
            const uint32_t* As = buf ? A1 : A0;
            const uint32_t* Bs = buf ? B1 : B0;
            if (nw == 0) mma_trees<7>(acc, As, Bs, mw, nw, lane);
            else         mma_trees<6>(acc, As, Bs, mw, nw, lane);
        }
        ++t;
    }

    /* epilogue: atomicAdd (undo x512 W scale); CTA 0 also adds the bias */
    const int ntiles = nw ? 6 : 7;
    const bool addb = (blockIdx.x == 0);
#pragma unroll
    for (int mi = 0; mi < 2; mi++) {
        int row = mw * 32 + mi * 16 + g;
        float* op0 = out + (size_t)row * C_SZ;
        float* op1 = out + (size_t)(row + 8) * C_SZ;
#pragma unroll
        for (int ni = 0; ni < 7; ni++) {
            if (ni >= ntiles) break;
            int col = nw * 56 + ni * 8 + tg * 2;
            if (col < C_SZ) {
                float bb = addb ? outb[col] : 0.f;
                atomicAdd(op0 + col, acc[mi][ni][0] * W_INV + bb);
                atomicAdd(op1 + col, acc[mi][ni][2] * W_INV + bb);
            }
            if (col + 1 < C_SZ) {
                float bb = addb ? outb[col + 1] : 0.f;
                atomicAdd(op0 + col + 1, acc[mi][ni][1] * W_INV + bb);
                atomicAdd(op1 + col + 1, acc[mi][ni][3] * W_INV + bb);
            }
        }
    }
}

extern "C" void kernel_launch(void* const* d_in, const int* in_sizes, int n_in,
                              void* d_out, int out_size) {
    const float* x    = (const float*)d_in[0];
    const float* selW = (const float*)d_in[1];
    const float* selb = (const float*)d_in[2];
    const float* outW = (const float*)d_in[3];
    const float* outb = (const float*)d_in[4];
    float* out = (float*)d_out;

    cudaMemsetAsync(out, 0, (size_t)out_size * sizeof(float));

    size_t sel_smem = (size_t)(128 + 64) * SST * 4;                  /* 52224 B */
    cudaFuncSetAttribute(sel_fp16, cudaFuncAttributeMaxDynamicSharedMemorySize, (int)sel_smem);
    dim3 g1(384, 4);
    sel_fp16<<<g1, 256, sel_smem>>>(x, selW, selb);

    size_t acc_smem = (size_t)(2 * 256 + 2 * N_PAD) * HST * 4;       /* 103680 B */
    cudaFuncSetAttribute(accum_512, cudaFuncAttributeMaxDynamicSharedMemorySize, (int)acc_smem);
    accum_512<<<NSLICE, 512, acc_smem>>>(outW, outb, out);
}